// round 8
// baseline (speedup 1.0000x reference)
#include <cuda_runtime.h>
#include <math.h>

// Problem constants
#define Bq  4
#define Lq  2048
#define Dq  1024
#define Hq  16
#define HDq 64

// Scratch (allocation-free rule: __device__ globals)
__device__ float g_q [(size_t)Bq * Lq * Dq];
__device__ float g_k [(size_t)Bq * Lq * Dq];
__device__ float g_v [(size_t)Bq * Lq * Dq];
__device__ float g_oh[(size_t)Bq * Lq * Dq];
// Fallback attention scratch in case d_out only holds `out`
__device__ float g_attn[(size_t)Bq * Hq * Lq * Lq];

// ---------------------------------------------------------------------------
// NT GEMM: C[m,n] = alpha * sum_k A[m,k]*B[n,k] (+bias[n])
// Both A and B are K-contiguous (row-major with K last). 128x128 tile, BK=8,
// 256 threads, 8x8 per-thread outputs via outer products. All dims assumed
// divisible by tile sizes (true for this problem).
// Batched over blockIdx.z with offset = (z/Hdiv)*s?1 + (z%Hdiv)*s?2.
// ---------------------------------------------------------------------------
__global__ __launch_bounds__(256)
void gemm_nt(const float* __restrict__ A, const float* __restrict__ B,
             float* __restrict__ C,
             int K, int lda, int ldb, int ldc,
             long long sA1, long long sA2,
             long long sB1, long long sB2,
             long long sC1, long long sC2, int Hdiv,
             float alpha, const float* __restrict__ bias)
{
    int z  = blockIdx.z;
    int bq = z / Hdiv, hq = z % Hdiv;
    A += (long long)bq * sA1 + (long long)hq * sA2;
    B += (long long)bq * sB1 + (long long)hq * sB2;
    C += (long long)bq * sC1 + (long long)hq * sC2;

    const int bm = blockIdx.y * 128;
    const int bn = blockIdx.x * 128;

    __shared__ float As[8][128];
    __shared__ float Bs[8][128];

    const int tid = threadIdx.x;
    const int tx  = tid & 15;     // N direction
    const int ty  = tid >> 4;     // M direction
    const int lr  = tid >> 1;     // load row (0..127)
    const int lk  = (tid & 1) << 2; // load k offset (0 or 4)

    const float* Ap = A + (long long)(bm + lr) * lda + lk;
    const float* Bp = B + (long long)(bn + lr) * ldb + lk;

    float acc[8][8];
#pragma unroll
    for (int i = 0; i < 8; i++)
#pragma unroll
        for (int j = 0; j < 8; j++) acc[i][j] = 0.f;

    for (int k0 = 0; k0 < K; k0 += 8) {
        float4 a4 = *(const float4*)(Ap + k0);
        float4 b4 = *(const float4*)(Bp + k0);
        __syncthreads();
        As[lk + 0][lr] = a4.x; As[lk + 1][lr] = a4.y;
        As[lk + 2][lr] = a4.z; As[lk + 3][lr] = a4.w;
        Bs[lk + 0][lr] = b4.x; Bs[lk + 1][lr] = b4.y;
        Bs[lk + 2][lr] = b4.z; Bs[lk + 3][lr] = b4.w;
        __syncthreads();
#pragma unroll
        for (int kk = 0; kk < 8; kk++) {
            float ar[8], br[8];
            *(float4*)(ar)     = *(const float4*)(&As[kk][ty * 4]);
            *(float4*)(ar + 4) = *(const float4*)(&As[kk][ty * 4 + 64]);
            *(float4*)(br)     = *(const float4*)(&Bs[kk][tx * 4]);
            *(float4*)(br + 4) = *(const float4*)(&Bs[kk][tx * 4 + 64]);
#pragma unroll
            for (int i = 0; i < 8; i++)
#pragma unroll
                for (int j = 0; j < 8; j++)
                    acc[i][j] = fmaf(ar[i], br[j], acc[i][j]);
        }
    }

#pragma unroll
    for (int ih = 0; ih < 2; ih++) {
#pragma unroll
        for (int i = 0; i < 4; i++) {
            int r = bm + ty * 4 + i + ih * 64;
#pragma unroll
            for (int jh = 0; jh < 2; jh++) {
                int c = bn + tx * 4 + jh * 64;
                float4 v;
                v.x = alpha * acc[ih * 4 + i][jh * 4 + 0];
                v.y = alpha * acc[ih * 4 + i][jh * 4 + 1];
                v.z = alpha * acc[ih * 4 + i][jh * 4 + 2];
                v.w = alpha * acc[ih * 4 + i][jh * 4 + 3];
                if (bias) {
                    v.x += bias[c + 0]; v.y += bias[c + 1];
                    v.z += bias[c + 2]; v.w += bias[c + 3];
                }
                *(float4*)(C + (long long)r * ldc + c) = v;
            }
        }
    }
}

// ---------------------------------------------------------------------------
// AV GEMM (NN): C[m,n] = sum_k P[m,k] * V[k,n] per (b,h) batch.
// M=2048 (l), N=64 (hd), K=2048 (t). P K-contiguous (lda=2048), V row stride
// Dq with n contiguous, C row stride Dq. 128x64 tile, BK=16, 256 threads,
// 8x4 per-thread outputs.
// ---------------------------------------------------------------------------
__global__ __launch_bounds__(256)
void gemm_av(const float* __restrict__ P, const float* __restrict__ V,
             float* __restrict__ C)
{
    int z  = blockIdx.z;
    int bq = z / Hq, hq = z % Hq;
    const float* Ab = P + (long long)z * Lq * Lq;
    const float* Bb = V + (long long)bq * Lq * Dq + hq * HDq;
    float*       Cb = C + (long long)bq * Lq * Dq + hq * HDq;

    const int bm = blockIdx.x * 128;

    __shared__ float As[16][128];
    __shared__ float Bs[16][64];

    const int tid = threadIdx.x;
    const int tx  = tid & 15;   // N (0..15 -> cols tx*4..)
    const int ty  = tid >> 4;   // M

    // A load mapping: two float4 per thread, same row, adjacent k-chunks
    const int arow = tid >> 1;
    const int ak0  = (tid & 1) * 8;   // 0 or 8

    float acc[8][4];
#pragma unroll
    for (int i = 0; i < 8; i++)
#pragma unroll
        for (int j = 0; j < 4; j++) acc[i][j] = 0.f;

    for (int k0 = 0; k0 < Lq; k0 += 16) {
        float4 a0 = *(const float4*)(Ab + (long long)(bm + arow) * Lq + k0 + ak0);
        float4 a1 = *(const float4*)(Ab + (long long)(bm + arow) * Lq + k0 + ak0 + 4);
        float4 b0 = *(const float4*)(Bb + (long long)(k0 + (tid >> 4)) * Dq + (tid & 15) * 4);
        __syncthreads();
        As[ak0 + 0][arow] = a0.x; As[ak0 + 1][arow] = a0.y;
        As[ak0 + 2][arow] = a0.z; As[ak0 + 3][arow] = a0.w;
        As[ak0 + 4][arow] = a1.x; As[ak0 + 5][arow] = a1.y;
        As[ak0 + 6][arow] = a1.z; As[ak0 + 7][arow] = a1.w;
        *(float4*)(&Bs[tid >> 4][(tid & 15) * 4]) = b0;
        __syncthreads();
#pragma unroll
        for (int kk = 0; kk < 16; kk++) {
            float ar[8];
            *(float4*)(ar)     = *(const float4*)(&As[kk][ty * 4]);
            *(float4*)(ar + 4) = *(const float4*)(&As[kk][ty * 4 + 64]);
            float4 b4 = *(const float4*)(&Bs[kk][tx * 4]);
            float br[4] = { b4.x, b4.y, b4.z, b4.w };
#pragma unroll
            for (int i = 0; i < 8; i++)
#pragma unroll
                for (int j = 0; j < 4; j++)
                    acc[i][j] = fmaf(ar[i], br[j], acc[i][j]);
        }
    }

#pragma unroll
    for (int ih = 0; ih < 2; ih++) {
#pragma unroll
        for (int i = 0; i < 4; i++) {
            int r = bm + ty * 4 + i + ih * 64;
            float4 v;
            v.x = acc[ih * 4 + i][0];
            v.y = acc[ih * 4 + i][1];
            v.z = acc[ih * 4 + i][2];
            v.w = acc[ih * 4 + i][3];
            *(float4*)(&Cb[(long long)r * Dq + tx * 4]) = v;
        }
    }
}

// ---------------------------------------------------------------------------
// Row softmax in place: one block (256 threads) per row of length 2048.
// ---------------------------------------------------------------------------
__global__ __launch_bounds__(256)
void softmax_rows(float* __restrict__ P)
{
    float* p = P + (long long)blockIdx.x * Lq;
    const int tid = threadIdx.x;

    float4 v0 = *(const float4*)(p + tid * 8);
    float4 v1 = *(const float4*)(p + tid * 8 + 4);
    float x[8] = { v0.x, v0.y, v0.z, v0.w, v1.x, v1.y, v1.z, v1.w };

    float m = x[0];
#pragma unroll
    for (int i = 1; i < 8; i++) m = fmaxf(m, x[i]);
#pragma unroll
    for (int o = 16; o; o >>= 1) m = fmaxf(m, __shfl_xor_sync(0xffffffffu, m, o));

    __shared__ float rmax[8];
    __shared__ float rsum[8];
    if ((tid & 31) == 0) rmax[tid >> 5] = m;
    __syncthreads();
    float bmax = rmax[0];
#pragma unroll
    for (int i = 1; i < 8; i++) bmax = fmaxf(bmax, rmax[i]);

    float s = 0.f;
#pragma unroll
    for (int i = 0; i < 8; i++) { x[i] = expf(x[i] - bmax); s += x[i]; }
#pragma unroll
    for (int o = 16; o; o >>= 1) s += __shfl_xor_sync(0xffffffffu, s, o);
    if ((tid & 31) == 0) rsum[tid >> 5] = s;
    __syncthreads();
    float tot = 0.f;
#pragma unroll
    for (int i = 0; i < 8; i++) tot += rsum[i];

    float inv = 1.0f / tot;
#pragma unroll
    for (int i = 0; i < 8; i++) x[i] *= inv;

    *(float4*)(p + tid * 8)     = make_float4(x[0], x[1], x[2], x[3]);
    *(float4*)(p + tid * 8 + 4) = make_float4(x[4], x[5], x[6], x[7]);
}

// ---------------------------------------------------------------------------
// Launch
// ---------------------------------------------------------------------------
extern "C" void kernel_launch(void* const* d_in, const int* in_sizes, int n_in,
                              void* d_out, int out_size)
{
    const float* query = (const float*)d_in[0];
    const float* key   = (const float*)d_in[1];
    const float* value = (const float*)d_in[2];
    const float* Wq    = (const float*)d_in[3];
    const float* Wk    = (const float*)d_in[4];
    const float* Wv    = (const float*)d_in[5];
    const float* Wo    = (const float*)d_in[6];
    const float* bo    = (const float*)d_in[7];

    float* out = (float*)d_out;

    const long long BLD  = (long long)Bq * Lq * Dq;              // 8,388,608
    const long long BHLL = (long long)Bq * Hq * Lq * Lq;         // 268,435,456

    float *pq, *pk, *pv, *poh, *pattn_scratch;
    cudaGetSymbolAddress((void**)&pq,  g_q);
    cudaGetSymbolAddress((void**)&pk,  g_k);
    cudaGetSymbolAddress((void**)&pv,  g_v);
    cudaGetSymbolAddress((void**)&poh, g_oh);
    cudaGetSymbolAddress((void**)&pattn_scratch, g_attn);

    // Output tuple (out, attention) concatenated; fall back to scratch if the
    // harness only allocated room for `out`.
    float* attn = ((long long)out_size >= BLD + BHLL) ? (out + BLD)
                                                      : pattn_scratch;

    dim3 blk(256);

    // 1) QKV projections: X[8192,1024] @ W^T[1024,1024]
    {
        dim3 grd(Dq / 128, (Bq * Lq) / 128, 1);
        gemm_nt<<<grd, blk>>>(query, Wq, pq, Dq, Dq, Dq, Dq,
                              0, 0, 0, 0, 0, 0, 1, 1.0f, (const float*)0);
        gemm_nt<<<grd, blk>>>(key,   Wk, pk, Dq, Dq, Dq, Dq,
                              0, 0, 0, 0, 0, 0, 1, 1.0f, (const float*)0);
        gemm_nt<<<grd, blk>>>(value, Wv, pv, Dq, Dq, Dq, Dq,
                              0, 0, 0, 0, 0, 0, 1, 1.0f, (const float*)0);
    }

    // 2) Scores: per (b,h): S = (1/8) * Q_bh @ K_bh^T -> attn region (raw)
    {
        dim3 grd(Lq / 128, Lq / 128, Bq * Hq);
        gemm_nt<<<grd, blk>>>(pq, pk, attn, HDq, Dq, Dq, Lq,
                              (long long)Lq * Dq, (long long)HDq,
                              (long long)Lq * Dq, (long long)HDq,
                              (long long)Hq * Lq * Lq, (long long)Lq * Lq,
                              Hq, 0.125f, (const float*)0);
    }

    // 3) Softmax in place over each length-2048 row
    softmax_rows<<<Bq * Hq * Lq, blk>>>(attn);

    // 4) out_head = attention @ V, written into [B,L,D] layout
    {
        dim3 grd(Lq / 128, 1, Bq * Hq);
        gemm_av<<<grd, blk>>>(attn, pv, poh);
    }

    // 5) Output projection: out = out_head @ Wo^T + bo
    {
        dim3 grd(Dq / 128, (Bq * Lq) / 128, 1);
        gemm_nt<<<grd, blk>>>(poh, Wo, out, Dq, Dq, Dq, Dq,
                              0, 0, 0, 0, 0, 0, 1, 1.0f, bo);
    }
}

// round 9
// speedup vs baseline: 1.0743x; 1.0743x over previous
#include <cuda_runtime.h>
#include <math.h>

// Problem constants
#define Bq  4
#define Lq  2048
#define Dq  1024
#define Hq  16
#define HDq 64

// Scratch (allocation-free rule: __device__ globals)
__device__ float g_q [(size_t)Bq * Lq * Dq];
__device__ float g_k [(size_t)Bq * Lq * Dq];
__device__ float g_v [(size_t)Bq * Lq * Dq];
__device__ float g_oh[(size_t)Bq * Lq * Dq];
// Fallback attention scratch in case d_out only holds `out`
__device__ float g_attn[(size_t)Bq * Hq * Lq * Lq];

// ---------------------------------------------------------------------------
// NT GEMM: C[m,n] = alpha * sum_k A[m,k]*B[n,k] (+bias[n])
// Both A and B are K-contiguous. 128x128 tile, BK=8, 256 threads, 8x8 outputs.
// Double-buffered smem (1 sync/iter) + register prefetch of next k-tile.
// Batched over blockIdx.z.
// ---------------------------------------------------------------------------
__global__ __launch_bounds__(256)
void gemm_nt(const float* __restrict__ A, const float* __restrict__ B,
             float* __restrict__ C,
             int K, int lda, int ldb, int ldc,
             long long sA1, long long sA2,
             long long sB1, long long sB2,
             long long sC1, long long sC2, int Hdiv,
             float alpha, const float* __restrict__ bias)
{
    int z  = blockIdx.z;
    int bq = z / Hdiv, hq = z % Hdiv;
    A += (long long)bq * sA1 + (long long)hq * sA2;
    B += (long long)bq * sB1 + (long long)hq * sB2;
    C += (long long)bq * sC1 + (long long)hq * sC2;

    const int bm = blockIdx.y * 128;
    const int bn = blockIdx.x * 128;

    __shared__ float As[2][8][128];
    __shared__ float Bs[2][8][128];

    const int tid = threadIdx.x;
    const int tx  = tid & 15;       // N direction
    const int ty  = tid >> 4;       // M direction
    const int lr  = tid >> 1;       // load row (0..127)
    const int lk  = (tid & 1) << 2; // load k offset (0 or 4)

    const float* Ap = A + (long long)(bm + lr) * lda + lk;
    const float* Bp = B + (long long)(bn + lr) * ldb + lk;

    float acc[8][8];
#pragma unroll
    for (int i = 0; i < 8; i++)
#pragma unroll
        for (int j = 0; j < 8; j++) acc[i][j] = 0.f;

    // Prologue: fill buffer 0
    float4 a4 = *(const float4*)(Ap);
    float4 b4 = *(const float4*)(Bp);
    As[0][lk + 0][lr] = a4.x; As[0][lk + 1][lr] = a4.y;
    As[0][lk + 2][lr] = a4.z; As[0][lk + 3][lr] = a4.w;
    Bs[0][lk + 0][lr] = b4.x; Bs[0][lk + 1][lr] = b4.y;
    Bs[0][lk + 2][lr] = b4.z; Bs[0][lk + 3][lr] = b4.w;
    __syncthreads();

    int p = 0;
    for (int k0 = 0; k0 < K; k0 += 8) {
        const bool nxt = (k0 + 8) < K;
        if (nxt) {
            a4 = *(const float4*)(Ap + k0 + 8);
            b4 = *(const float4*)(Bp + k0 + 8);
        }
#pragma unroll
        for (int kk = 0; kk < 8; kk++) {
            float ar[8], br[8];
            *(float4*)(ar)     = *(const float4*)(&As[p][kk][ty * 4]);
            *(float4*)(ar + 4) = *(const float4*)(&As[p][kk][ty * 4 + 64]);
            *(float4*)(br)     = *(const float4*)(&Bs[p][kk][tx * 4]);
            *(float4*)(br + 4) = *(const float4*)(&Bs[p][kk][tx * 4 + 64]);
#pragma unroll
            for (int i = 0; i < 8; i++)
#pragma unroll
                for (int j = 0; j < 8; j++)
                    acc[i][j] = fmaf(ar[i], br[j], acc[i][j]);
        }
        if (nxt) {
            p ^= 1;
            As[p][lk + 0][lr] = a4.x; As[p][lk + 1][lr] = a4.y;
            As[p][lk + 2][lr] = a4.z; As[p][lk + 3][lr] = a4.w;
            Bs[p][lk + 0][lr] = b4.x; Bs[p][lk + 1][lr] = b4.y;
            Bs[p][lk + 2][lr] = b4.z; Bs[p][lk + 3][lr] = b4.w;
            __syncthreads();
        }
    }

#pragma unroll
    for (int ih = 0; ih < 2; ih++) {
#pragma unroll
        for (int i = 0; i < 4; i++) {
            int r = bm + ty * 4 + i + ih * 64;
#pragma unroll
            for (int jh = 0; jh < 2; jh++) {
                int c = bn + tx * 4 + jh * 64;
                float4 v;
                v.x = alpha * acc[ih * 4 + i][jh * 4 + 0];
                v.y = alpha * acc[ih * 4 + i][jh * 4 + 1];
                v.z = alpha * acc[ih * 4 + i][jh * 4 + 2];
                v.w = alpha * acc[ih * 4 + i][jh * 4 + 3];
                if (bias) {
                    v.x += bias[c + 0]; v.y += bias[c + 1];
                    v.z += bias[c + 2]; v.w += bias[c + 3];
                }
                *(float4*)(C + (long long)r * ldc + c) = v;
            }
        }
    }
}

// ---------------------------------------------------------------------------
// AV GEMM (NN): C[m,n] = sum_k P[m,k] * V[k,n] per (b,h) batch.
// M=2048 (l), N=64 (hd), K=2048 (t). 128x64 tile, BK=8, 128 threads,
// 8x8 per-thread outputs (FMA:LDS = 16). Double-buffered + prefetch.
// ---------------------------------------------------------------------------
__global__ __launch_bounds__(128)
void gemm_av(const float* __restrict__ P, const float* __restrict__ V,
             float* __restrict__ C)
{
    int z  = blockIdx.z;
    int bq = z / Hq, hq = z % Hq;
    const float* Ab = P + (long long)z * Lq * Lq;
    const float* Bb = V + (long long)bq * Lq * Dq + hq * HDq;
    float*       Cb = C + (long long)bq * Lq * Dq + hq * HDq;

    const int bm = blockIdx.x * 128;

    __shared__ float As[2][8][128];
    __shared__ float Bs[2][8][64];

    const int tid = threadIdx.x;
    const int tx  = tid & 7;    // N: cols tx*4 and 32+tx*4
    const int ty  = tid >> 3;   // M: rows ty*4.. and 64+ty*4..

    // A loader: one row per thread (bm+tid), 8 k-floats = 2 float4
    const float* Ap = Ab + (long long)(bm + tid) * Lq;
    // B loader: row tid>>4 (0..7), col (tid&15)*4
    const int bvr = tid >> 4;
    const int bvc = (tid & 15) * 4;
    const float* Bp = Bb + (long long)bvr * Dq + bvc;

    float acc[8][8];
#pragma unroll
    for (int i = 0; i < 8; i++)
#pragma unroll
        for (int j = 0; j < 8; j++) acc[i][j] = 0.f;

    // Prologue: fill buffer 0
    float4 a0 = *(const float4*)(Ap);
    float4 a1 = *(const float4*)(Ap + 4);
    float4 b0 = *(const float4*)(Bp);
    As[0][0][tid] = a0.x; As[0][1][tid] = a0.y;
    As[0][2][tid] = a0.z; As[0][3][tid] = a0.w;
    As[0][4][tid] = a1.x; As[0][5][tid] = a1.y;
    As[0][6][tid] = a1.z; As[0][7][tid] = a1.w;
    *(float4*)(&Bs[0][bvr][bvc]) = b0;
    __syncthreads();

    int p = 0;
    for (int k0 = 0; k0 < Lq; k0 += 8) {
        const bool nxt = (k0 + 8) < Lq;
        if (nxt) {
            a0 = *(const float4*)(Ap + k0 + 8);
            a1 = *(const float4*)(Ap + k0 + 12);
            b0 = *(const float4*)(Bp + (long long)(k0 + 8) * Dq);
        }
#pragma unroll
        for (int kk = 0; kk < 8; kk++) {
            float ar[8], br[8];
            *(float4*)(ar)     = *(const float4*)(&As[p][kk][ty * 4]);
            *(float4*)(ar + 4) = *(const float4*)(&As[p][kk][ty * 4 + 64]);
            *(float4*)(br)     = *(const float4*)(&Bs[p][kk][tx * 4]);
            *(float4*)(br + 4) = *(const float4*)(&Bs[p][kk][tx * 4 + 32]);
#pragma unroll
            for (int i = 0; i < 8; i++)
#pragma unroll
                for (int j = 0; j < 8; j++)
                    acc[i][j] = fmaf(ar[i], br[j], acc[i][j]);
        }
        if (nxt) {
            p ^= 1;
            As[p][0][tid] = a0.x; As[p][1][tid] = a0.y;
            As[p][2][tid] = a0.z; As[p][3][tid] = a0.w;
            As[p][4][tid] = a1.x; As[p][5][tid] = a1.y;
            As[p][6][tid] = a1.z; As[p][7][tid] = a1.w;
            *(float4*)(&Bs[p][bvr][bvc]) = b0;
            __syncthreads();
        }
    }

#pragma unroll
    for (int ih = 0; ih < 2; ih++) {
#pragma unroll
        for (int i = 0; i < 4; i++) {
            int r = bm + ih * 64 + ty * 4 + i;
            float4 v0, v1;
            v0.x = acc[ih * 4 + i][0]; v0.y = acc[ih * 4 + i][1];
            v0.z = acc[ih * 4 + i][2]; v0.w = acc[ih * 4 + i][3];
            v1.x = acc[ih * 4 + i][4]; v1.y = acc[ih * 4 + i][5];
            v1.z = acc[ih * 4 + i][6]; v1.w = acc[ih * 4 + i][7];
            *(float4*)(&Cb[(long long)r * Dq + tx * 4])      = v0;
            *(float4*)(&Cb[(long long)r * Dq + 32 + tx * 4]) = v1;
        }
    }
}

// ---------------------------------------------------------------------------
// Row softmax in place: one block (256 threads) per row of length 2048.
// ---------------------------------------------------------------------------
__global__ __launch_bounds__(256)
void softmax_rows(float* __restrict__ P)
{
    float* p = P + (long long)blockIdx.x * Lq;
    const int tid = threadIdx.x;

    float4 v0 = *(const float4*)(p + tid * 8);
    float4 v1 = *(const float4*)(p + tid * 8 + 4);
    float x[8] = { v0.x, v0.y, v0.z, v0.w, v1.x, v1.y, v1.z, v1.w };

    float m = x[0];
#pragma unroll
    for (int i = 1; i < 8; i++) m = fmaxf(m, x[i]);
#pragma unroll
    for (int o = 16; o; o >>= 1) m = fmaxf(m, __shfl_xor_sync(0xffffffffu, m, o));

    __shared__ float rmax[8];
    __shared__ float rsum[8];
    if ((tid & 31) == 0) rmax[tid >> 5] = m;
    __syncthreads();
    float bmax = rmax[0];
#pragma unroll
    for (int i = 1; i < 8; i++) bmax = fmaxf(bmax, rmax[i]);

    float s = 0.f;
#pragma unroll
    for (int i = 0; i < 8; i++) { x[i] = expf(x[i] - bmax); s += x[i]; }
#pragma unroll
    for (int o = 16; o; o >>= 1) s += __shfl_xor_sync(0xffffffffu, s, o);
    if ((tid & 31) == 0) rsum[tid >> 5] = s;
    __syncthreads();
    float tot = 0.f;
#pragma unroll
    for (int i = 0; i < 8; i++) tot += rsum[i];

    float inv = 1.0f / tot;
#pragma unroll
    for (int i = 0; i < 8; i++) x[i] *= inv;

    *(float4*)(p + tid * 8)     = make_float4(x[0], x[1], x[2], x[3]);
    *(float4*)(p + tid * 8 + 4) = make_float4(x[4], x[5], x[6], x[7]);
}

// ---------------------------------------------------------------------------
// Launch
// ---------------------------------------------------------------------------
extern "C" void kernel_launch(void* const* d_in, const int* in_sizes, int n_in,
                              void* d_out, int out_size)
{
    const float* query = (const float*)d_in[0];
    const float* key   = (const float*)d_in[1];
    const float* value = (const float*)d_in[2];
    const float* Wq    = (const float*)d_in[3];
    const float* Wk    = (const float*)d_in[4];
    const float* Wv    = (const float*)d_in[5];
    const float* Wo    = (const float*)d_in[6];
    const float* bo    = (const float*)d_in[7];

    float* out = (float*)d_out;

    const long long BLD  = (long long)Bq * Lq * Dq;              // 8,388,608
    const long long BHLL = (long long)Bq * Hq * Lq * Lq;         // 268,435,456

    float *pq, *pk, *pv, *poh, *pattn_scratch;
    cudaGetSymbolAddress((void**)&pq,  g_q);
    cudaGetSymbolAddress((void**)&pk,  g_k);
    cudaGetSymbolAddress((void**)&pv,  g_v);
    cudaGetSymbolAddress((void**)&poh, g_oh);
    cudaGetSymbolAddress((void**)&pattn_scratch, g_attn);

    float* attn = ((long long)out_size >= BLD + BHLL) ? (out + BLD)
                                                      : pattn_scratch;

    dim3 blk(256);

    // 1) QKV projections: X[8192,1024] @ W^T[1024,1024]
    {
        dim3 grd(Dq / 128, (Bq * Lq) / 128, 1);
        gemm_nt<<<grd, blk>>>(query, Wq, pq, Dq, Dq, Dq, Dq,
                              0, 0, 0, 0, 0, 0, 1, 1.0f, (const float*)0);
        gemm_nt<<<grd, blk>>>(key,   Wk, pk, Dq, Dq, Dq, Dq,
                              0, 0, 0, 0, 0, 0, 1, 1.0f, (const float*)0);
        gemm_nt<<<grd, blk>>>(value, Wv, pv, Dq, Dq, Dq, Dq,
                              0, 0, 0, 0, 0, 0, 1, 1.0f, (const float*)0);
    }

    // 2) Scores: per (b,h): S = (1/8) * Q_bh @ K_bh^T
    {
        dim3 grd(Lq / 128, Lq / 128, Bq * Hq);
        gemm_nt<<<grd, blk>>>(pq, pk, attn, HDq, Dq, Dq, Lq,
                              (long long)Lq * Dq, (long long)HDq,
                              (long long)Lq * Dq, (long long)HDq,
                              (long long)Hq * Lq * Lq, (long long)Lq * Lq,
                              Hq, 0.125f, (const float*)0);
    }

    // 3) Softmax in place over each length-2048 row
    softmax_rows<<<Bq * Hq * Lq, blk>>>(attn);

    // 4) out_head = attention @ V, written into [B,L,D] layout
    {
        dim3 grd(Lq / 128, 1, Bq * Hq);
        gemm_av<<<grd, dim3(128)>>>(attn, pv, poh);
    }

    // 5) Output projection: out = out_head @ Wo^T + bo
    {
        dim3 grd(Dq / 128, (Bq * Lq) / 128, 1);
        gemm_nt<<<grd, blk>>>(poh, Wo, out, Dq, Dq, Dq, Dq,
                              0, 0, 0, 0, 0, 0, 1, 1.0f, bo);
    }
}

// round 10
// speedup vs baseline: 1.1330x; 1.0546x over previous
#include <cuda_runtime.h>
#include <math.h>

// Problem constants
#define Bq  4
#define Lq  2048
#define Dq  1024
#define Hq  16
#define HDq 64

typedef unsigned long long u64;

// Scratch (allocation-free rule: __device__ globals)
__device__ float g_q [(size_t)Bq * Lq * Dq];
__device__ float g_k [(size_t)Bq * Lq * Dq];
__device__ float g_v [(size_t)Bq * Lq * Dq];
__device__ float g_oh[(size_t)Bq * Lq * Dq];
// Fallback attention scratch in case d_out only holds `out`
__device__ float g_attn[(size_t)Bq * Hq * Lq * Lq];

// ---------------------------------------------------------------------------
// Packed f32x2 helpers (Blackwell sm_103a): one instruction = two fp32 ops.
// Rounding identical to two scalar fmaf/mul/add (rn each lane).
// ---------------------------------------------------------------------------
__device__ __forceinline__ void fma2(u64& d, u64 a, u64 b) {
    asm("fma.rn.f32x2 %0, %1, %2, %0;" : "+l"(d) : "l"(a), "l"(b));
}
__device__ __forceinline__ void mul2(u64& d, u64 a, u64 b) {
    asm("mul.rn.f32x2 %0, %1, %2;" : "=l"(d) : "l"(a), "l"(b));
}
__device__ __forceinline__ void add2(u64& d, u64 a, u64 b) {
    asm("add.rn.f32x2 %0, %1, %2;" : "=l"(d) : "l"(a), "l"(b));
}
__device__ __forceinline__ u64 dup2(float x) {
    u64 r;
    asm("mov.b64 %0, {%1, %1};" : "=l"(r) : "f"(x));
    return r;
}

// ---------------------------------------------------------------------------
// NT GEMM: C[m,n] = alpha * sum_k A[m,k]*B[n,k] (+bias[n])
// Both A and B K-contiguous. 128x128 tile, BK=8, 256 threads, 8x8 outputs
// held as 8x4 packed f32x2 accumulators. Double-buffered smem + reg prefetch.
// ---------------------------------------------------------------------------
__global__ __launch_bounds__(256)
void gemm_nt(const float* __restrict__ A, const float* __restrict__ B,
             float* __restrict__ C,
             int K, int lda, int ldb, int ldc,
             long long sA1, long long sA2,
             long long sB1, long long sB2,
             long long sC1, long long sC2, int Hdiv,
             float alpha, const float* __restrict__ bias)
{
    int z  = blockIdx.z;
    int bq = z / Hdiv, hq = z % Hdiv;
    A += (long long)bq * sA1 + (long long)hq * sA2;
    B += (long long)bq * sB1 + (long long)hq * sB2;
    C += (long long)bq * sC1 + (long long)hq * sC2;

    const int bm = blockIdx.y * 128;
    const int bn = blockIdx.x * 128;

    __shared__ float As[2][8][128];
    __shared__ float Bs[2][8][128];

    const int tid = threadIdx.x;
    const int tx  = tid & 15;       // N direction
    const int ty  = tid >> 4;       // M direction
    const int lr  = tid >> 1;       // load row (0..127)
    const int lk  = (tid & 1) << 2; // load k offset (0 or 4)

    const float* Ap = A + (long long)(bm + lr) * lda + lk;
    const float* Bp = B + (long long)(bn + lr) * ldb + lk;

    // acc[i][0..1] -> cols tx*4+{0..3}; acc[i][2..3] -> cols tx*4+64+{0..3}
    u64 acc[8][4];
#pragma unroll
    for (int i = 0; i < 8; i++)
#pragma unroll
        for (int j = 0; j < 4; j++) acc[i][j] = 0ull;

    // Prologue: fill buffer 0
    float4 a4 = *(const float4*)(Ap);
    float4 b4 = *(const float4*)(Bp);
    As[0][lk + 0][lr] = a4.x; As[0][lk + 1][lr] = a4.y;
    As[0][lk + 2][lr] = a4.z; As[0][lk + 3][lr] = a4.w;
    Bs[0][lk + 0][lr] = b4.x; Bs[0][lk + 1][lr] = b4.y;
    Bs[0][lk + 2][lr] = b4.z; Bs[0][lk + 3][lr] = b4.w;
    __syncthreads();

    int p = 0;
    for (int k0 = 0; k0 < K; k0 += 8) {
        const bool nxt = (k0 + 8) < K;
        if (nxt) {
            a4 = *(const float4*)(Ap + k0 + 8);
            b4 = *(const float4*)(Bp + k0 + 8);
        }
#pragma unroll
        for (int kk = 0; kk < 8; kk++) {
            float ar[8];
            *(float4*)(ar)     = *(const float4*)(&As[p][kk][ty * 4]);
            *(float4*)(ar + 4) = *(const float4*)(&As[p][kk][ty * 4 + 64]);
            ulonglong2 bl0 = *(const ulonglong2*)(&Bs[p][kk][tx * 4]);
            ulonglong2 bl1 = *(const ulonglong2*)(&Bs[p][kk][tx * 4 + 64]);
            u64 bb[4] = { bl0.x, bl0.y, bl1.x, bl1.y };
#pragma unroll
            for (int i = 0; i < 8; i++) {
                u64 ad = dup2(ar[i]);
#pragma unroll
                for (int j = 0; j < 4; j++) fma2(acc[i][j], ad, bb[j]);
            }
        }
        if (nxt) {
            p ^= 1;
            As[p][lk + 0][lr] = a4.x; As[p][lk + 1][lr] = a4.y;
            As[p][lk + 2][lr] = a4.z; As[p][lk + 3][lr] = a4.w;
            Bs[p][lk + 0][lr] = b4.x; Bs[p][lk + 1][lr] = b4.y;
            Bs[p][lk + 2][lr] = b4.z; Bs[p][lk + 3][lr] = b4.w;
            __syncthreads();
        }
    }

    u64 alpha2 = dup2(alpha);
#pragma unroll
    for (int ih = 0; ih < 2; ih++) {
#pragma unroll
        for (int i = 0; i < 4; i++) {
            int r = bm + ty * 4 + i + ih * 64;
#pragma unroll
            for (int jh = 0; jh < 2; jh++) {
                int c = bn + tx * 4 + jh * 64;
                u64 v0 = acc[ih * 4 + i][jh * 2 + 0];
                u64 v1 = acc[ih * 4 + i][jh * 2 + 1];
                mul2(v0, v0, alpha2);
                mul2(v1, v1, alpha2);
                if (bias) {
                    ulonglong2 bb = *(const ulonglong2*)(&bias[c]);
                    add2(v0, v0, bb.x);
                    add2(v1, v1, bb.y);
                }
                ulonglong2 ov; ov.x = v0; ov.y = v1;
                *(ulonglong2*)(C + (long long)r * ldc + c) = ov;
            }
        }
    }
}

// ---------------------------------------------------------------------------
// AV GEMM (NN): C[m,n] = sum_k P[m,k] * V[k,n] per (b,h) batch.
// M=2048, N=64, K=2048. 128x64 tile, BK=8, 128 threads, 8x8 outputs as
// 8x4 packed f32x2 accumulators. Double-buffered + prefetch.
// ---------------------------------------------------------------------------
__global__ __launch_bounds__(128)
void gemm_av(const float* __restrict__ P, const float* __restrict__ V,
             float* __restrict__ C)
{
    int z  = blockIdx.z;
    int bq = z / Hq, hq = z % Hq;
    const float* Ab = P + (long long)z * Lq * Lq;
    const float* Bb = V + (long long)bq * Lq * Dq + hq * HDq;
    float*       Cb = C + (long long)bq * Lq * Dq + hq * HDq;

    const int bm = blockIdx.x * 128;

    __shared__ float As[2][8][128];
    __shared__ float Bs[2][8][64];

    const int tid = threadIdx.x;
    const int tx  = tid & 7;    // N: cols tx*4 and 32+tx*4
    const int ty  = tid >> 3;   // M: rows ty*4.. and 64+ty*4..

    const float* Ap = Ab + (long long)(bm + tid) * Lq;
    const int bvr = tid >> 4;
    const int bvc = (tid & 15) * 4;
    const float* Bp = Bb + (long long)bvr * Dq + bvc;

    u64 acc[8][4];
#pragma unroll
    for (int i = 0; i < 8; i++)
#pragma unroll
        for (int j = 0; j < 4; j++) acc[i][j] = 0ull;

    // Prologue: fill buffer 0
    float4 a0 = *(const float4*)(Ap);
    float4 a1 = *(const float4*)(Ap + 4);
    float4 b0 = *(const float4*)(Bp);
    As[0][0][tid] = a0.x; As[0][1][tid] = a0.y;
    As[0][2][tid] = a0.z; As[0][3][tid] = a0.w;
    As[0][4][tid] = a1.x; As[0][5][tid] = a1.y;
    As[0][6][tid] = a1.z; As[0][7][tid] = a1.w;
    *(float4*)(&Bs[0][bvr][bvc]) = b0;
    __syncthreads();

    int p = 0;
    for (int k0 = 0; k0 < Lq; k0 += 8) {
        const bool nxt = (k0 + 8) < Lq;
        if (nxt) {
            a0 = *(const float4*)(Ap + k0 + 8);
            a1 = *(const float4*)(Ap + k0 + 12);
            b0 = *(const float4*)(Bp + (long long)(k0 + 8) * Dq);
        }
#pragma unroll
        for (int kk = 0; kk < 8; kk++) {
            float ar[8];
            *(float4*)(ar)     = *(const float4*)(&As[p][kk][ty * 4]);
            *(float4*)(ar + 4) = *(const float4*)(&As[p][kk][ty * 4 + 64]);
            ulonglong2 bl0 = *(const ulonglong2*)(&Bs[p][kk][tx * 4]);
            ulonglong2 bl1 = *(const ulonglong2*)(&Bs[p][kk][tx * 4 + 32]);
            u64 bb[4] = { bl0.x, bl0.y, bl1.x, bl1.y };
#pragma unroll
            for (int i = 0; i < 8; i++) {
                u64 ad = dup2(ar[i]);
#pragma unroll
                for (int j = 0; j < 4; j++) fma2(acc[i][j], ad, bb[j]);
            }
        }
        if (nxt) {
            p ^= 1;
            As[p][0][tid] = a0.x; As[p][1][tid] = a0.y;
            As[p][2][tid] = a0.z; As[p][3][tid] = a0.w;
            As[p][4][tid] = a1.x; As[p][5][tid] = a1.y;
            As[p][6][tid] = a1.z; As[p][7][tid] = a1.w;
            *(float4*)(&Bs[p][bvr][bvc]) = b0;
            __syncthreads();
        }
    }

#pragma unroll
    for (int ih = 0; ih < 2; ih++) {
#pragma unroll
        for (int i = 0; i < 4; i++) {
            int r = bm + ih * 64 + ty * 4 + i;
            ulonglong2 ov0, ov1;
            ov0.x = acc[ih * 4 + i][0]; ov0.y = acc[ih * 4 + i][1];
            ov1.x = acc[ih * 4 + i][2]; ov1.y = acc[ih * 4 + i][3];
            *(ulonglong2*)(&Cb[(long long)r * Dq + tx * 4])      = ov0;
            *(ulonglong2*)(&Cb[(long long)r * Dq + 32 + tx * 4]) = ov1;
        }
    }
}

// ---------------------------------------------------------------------------
// Row softmax in place: one block (256 threads) per row of length 2048.
// ---------------------------------------------------------------------------
__global__ __launch_bounds__(256)
void softmax_rows(float* __restrict__ P)
{
    float* p = P + (long long)blockIdx.x * Lq;
    const int tid = threadIdx.x;

    float4 v0 = *(const float4*)(p + tid * 8);
    float4 v1 = *(const float4*)(p + tid * 8 + 4);
    float x[8] = { v0.x, v0.y, v0.z, v0.w, v1.x, v1.y, v1.z, v1.w };

    float m = x[0];
#pragma unroll
    for (int i = 1; i < 8; i++) m = fmaxf(m, x[i]);
#pragma unroll
    for (int o = 16; o; o >>= 1) m = fmaxf(m, __shfl_xor_sync(0xffffffffu, m, o));

    __shared__ float rmax[8];
    __shared__ float rsum[8];
    if ((tid & 31) == 0) rmax[tid >> 5] = m;
    __syncthreads();
    float bmax = rmax[0];
#pragma unroll
    for (int i = 1; i < 8; i++) bmax = fmaxf(bmax, rmax[i]);

    float s = 0.f;
#pragma unroll
    for (int i = 0; i < 8; i++) { x[i] = expf(x[i] - bmax); s += x[i]; }
#pragma unroll
    for (int o = 16; o; o >>= 1) s += __shfl_xor_sync(0xffffffffu, s, o);
    if ((tid & 31) == 0) rsum[tid >> 5] = s;
    __syncthreads();
    float tot = 0.f;
#pragma unroll
    for (int i = 0; i < 8; i++) tot += rsum[i];

    float inv = 1.0f / tot;
#pragma unroll
    for (int i = 0; i < 8; i++) x[i] *= inv;

    *(float4*)(p + tid * 8)     = make_float4(x[0], x[1], x[2], x[3]);
    *(float4*)(p + tid * 8 + 4) = make_float4(x[4], x[5], x[6], x[7]);
}

// ---------------------------------------------------------------------------
// Launch
// ---------------------------------------------------------------------------
extern "C" void kernel_launch(void* const* d_in, const int* in_sizes, int n_in,
                              void* d_out, int out_size)
{
    const float* query = (const float*)d_in[0];
    const float* key   = (const float*)d_in[1];
    const float* value = (const float*)d_in[2];
    const float* Wq    = (const float*)d_in[3];
    const float* Wk    = (const float*)d_in[4];
    const float* Wv    = (const float*)d_in[5];
    const float* Wo    = (const float*)d_in[6];
    const float* bo    = (const float*)d_in[7];

    float* out = (float*)d_out;

    const long long BLD  = (long long)Bq * Lq * Dq;              // 8,388,608
    const long long BHLL = (long long)Bq * Hq * Lq * Lq;         // 268,435,456

    float *pq, *pk, *pv, *poh, *pattn_scratch;
    cudaGetSymbolAddress((void**)&pq,  g_q);
    cudaGetSymbolAddress((void**)&pk,  g_k);
    cudaGetSymbolAddress((void**)&pv,  g_v);
    cudaGetSymbolAddress((void**)&poh, g_oh);
    cudaGetSymbolAddress((void**)&pattn_scratch, g_attn);

    float* attn = ((long long)out_size >= BLD + BHLL) ? (out + BLD)
                                                      : pattn_scratch;

    dim3 blk(256);

    // 1) QKV projections: X[8192,1024] @ W^T[1024,1024]
    {
        dim3 grd(Dq / 128, (Bq * Lq) / 128, 1);
        gemm_nt<<<grd, blk>>>(query, Wq, pq, Dq, Dq, Dq, Dq,
                              0, 0, 0, 0, 0, 0, 1, 1.0f, (const float*)0);
        gemm_nt<<<grd, blk>>>(key,   Wk, pk, Dq, Dq, Dq, Dq,
                              0, 0, 0, 0, 0, 0, 1, 1.0f, (const float*)0);
        gemm_nt<<<grd, blk>>>(value, Wv, pv, Dq, Dq, Dq, Dq,
                              0, 0, 0, 0, 0, 0, 1, 1.0f, (const float*)0);
    }

    // 2) Scores: per (b,h): S = (1/8) * Q_bh @ K_bh^T
    {
        dim3 grd(Lq / 128, Lq / 128, Bq * Hq);
        gemm_nt<<<grd, blk>>>(pq, pk, attn, HDq, Dq, Dq, Lq,
                              (long long)Lq * Dq, (long long)HDq,
                              (long long)Lq * Dq, (long long)HDq,
                              (long long)Hq * Lq * Lq, (long long)Lq * Lq,
                              Hq, 0.125f, (const float*)0);
    }

    // 3) Softmax in place over each length-2048 row
    softmax_rows<<<Bq * Hq * Lq, blk>>>(attn);

    // 4) out_head = attention @ V, written into [B,L,D] layout
    {
        dim3 grd(Lq / 128, 1, Bq * Hq);
        gemm_av<<<grd, dim3(128)>>>(attn, pv, poh);
    }

    // 5) Output projection: out = out_head @ Wo^T + bo
    {
        dim3 grd(Dq / 128, (Bq * Lq) / 128, 1);
        gemm_nt<<<grd, blk>>>(poh, Wo, out, Dq, Dq, Dq, Dq,
                              0, 0, 0, 0, 0, 0, 1, 1.0f, bo);
    }
}

// round 11
// speedup vs baseline: 1.1365x; 1.0031x over previous
#include <cuda_runtime.h>
#include <math.h>

// Problem constants
#define Bq  4
#define Lq  2048
#define Dq  1024
#define Hq  16
#define HDq 64

typedef unsigned long long u64;

// Scratch (allocation-free rule: __device__ globals)
__device__ float g_q [(size_t)Bq * Lq * Dq];
__device__ float g_k [(size_t)Bq * Lq * Dq];
__device__ float g_v [(size_t)Bq * Lq * Dq];
__device__ float g_oh[(size_t)Bq * Lq * Dq];
// Fallback attention scratch in case d_out only holds `out`
__device__ float g_attn[(size_t)Bq * Hq * Lq * Lq];

// ---------------------------------------------------------------------------
// Packed f32x2 helpers (Blackwell sm_103a): one instruction = two fp32 ops.
// Rounding identical to two scalar fmaf/mul/add (rn each lane).
// ---------------------------------------------------------------------------
__device__ __forceinline__ void fma2(u64& d, u64 a, u64 b) {
    asm("fma.rn.f32x2 %0, %1, %2, %0;" : "+l"(d) : "l"(a), "l"(b));
}
__device__ __forceinline__ void mul2(u64& d, u64 a, u64 b) {
    asm("mul.rn.f32x2 %0, %1, %2;" : "=l"(d) : "l"(a), "l"(b));
}
__device__ __forceinline__ void add2(u64& d, u64 a, u64 b) {
    asm("add.rn.f32x2 %0, %1, %2;" : "=l"(d) : "l"(a), "l"(b));
}
__device__ __forceinline__ u64 dup2(float x) {
    u64 r;
    asm("mov.b64 %0, {%1, %1};" : "=l"(r) : "f"(x));
    return r;
}

// ---------------------------------------------------------------------------
// NT GEMM: C[m,n] = alpha * sum_k A[m,k]*B[n,k] (+bias[n])
// Both A and B K-contiguous. 128x128 tile, BK=8, 256 threads, 8x8 outputs
// held as 8x4 packed f32x2 accumulators. Double-buffered smem + reg prefetch.
// ---------------------------------------------------------------------------
__global__ __launch_bounds__(256)
void gemm_nt(const float* __restrict__ A, const float* __restrict__ B,
             float* __restrict__ C,
             int K, int lda, int ldb, int ldc,
             long long sA1, long long sA2,
             long long sB1, long long sB2,
             long long sC1, long long sC2, int Hdiv,
             float alpha, const float* __restrict__ bias)
{
    int z  = blockIdx.z;
    int bq = z / Hdiv, hq = z % Hdiv;
    A += (long long)bq * sA1 + (long long)hq * sA2;
    B += (long long)bq * sB1 + (long long)hq * sB2;
    C += (long long)bq * sC1 + (long long)hq * sC2;

    const int bm = blockIdx.y * 128;
    const int bn = blockIdx.x * 128;

    __shared__ float As[2][8][128];
    __shared__ float Bs[2][8][128];

    const int tid = threadIdx.x;
    const int tx  = tid & 15;       // N direction
    const int ty  = tid >> 4;       // M direction
    const int lr  = tid >> 1;       // load row (0..127)
    const int lk  = (tid & 1) << 2; // load k offset (0 or 4)

    const float* Ap = A + (long long)(bm + lr) * lda + lk;
    const float* Bp = B + (long long)(bn + lr) * ldb + lk;

    // acc[i][0..1] -> cols tx*4+{0..3}; acc[i][2..3] -> cols tx*4+64+{0..3}
    u64 acc[8][4];
#pragma unroll
    for (int i = 0; i < 8; i++)
#pragma unroll
        for (int j = 0; j < 4; j++) acc[i][j] = 0ull;

    // Prologue: fill buffer 0
    float4 a4 = *(const float4*)(Ap);
    float4 b4 = *(const float4*)(Bp);
    As[0][lk + 0][lr] = a4.x; As[0][lk + 1][lr] = a4.y;
    As[0][lk + 2][lr] = a4.z; As[0][lk + 3][lr] = a4.w;
    Bs[0][lk + 0][lr] = b4.x; Bs[0][lk + 1][lr] = b4.y;
    Bs[0][lk + 2][lr] = b4.z; Bs[0][lk + 3][lr] = b4.w;
    __syncthreads();

    int p = 0;
    for (int k0 = 0; k0 < K; k0 += 8) {
        const bool nxt = (k0 + 8) < K;
        if (nxt) {
            a4 = *(const float4*)(Ap + k0 + 8);
            b4 = *(const float4*)(Bp + k0 + 8);
        }
#pragma unroll
        for (int kk = 0; kk < 8; kk++) {
            float ar[8];
            *(float4*)(ar)     = *(const float4*)(&As[p][kk][ty * 4]);
            *(float4*)(ar + 4) = *(const float4*)(&As[p][kk][ty * 4 + 64]);
            ulonglong2 bl0 = *(const ulonglong2*)(&Bs[p][kk][tx * 4]);
            ulonglong2 bl1 = *(const ulonglong2*)(&Bs[p][kk][tx * 4 + 64]);
            u64 bb[4] = { bl0.x, bl0.y, bl1.x, bl1.y };
#pragma unroll
            for (int i = 0; i < 8; i++) {
                u64 ad = dup2(ar[i]);
#pragma unroll
                for (int j = 0; j < 4; j++) fma2(acc[i][j], ad, bb[j]);
            }
        }
        if (nxt) {
            p ^= 1;
            As[p][lk + 0][lr] = a4.x; As[p][lk + 1][lr] = a4.y;
            As[p][lk + 2][lr] = a4.z; As[p][lk + 3][lr] = a4.w;
            Bs[p][lk + 0][lr] = b4.x; Bs[p][lk + 1][lr] = b4.y;
            Bs[p][lk + 2][lr] = b4.z; Bs[p][lk + 3][lr] = b4.w;
            __syncthreads();
        }
    }

    u64 alpha2 = dup2(alpha);
#pragma unroll
    for (int ih = 0; ih < 2; ih++) {
#pragma unroll
        for (int i = 0; i < 4; i++) {
            int r = bm + ty * 4 + i + ih * 64;
#pragma unroll
            for (int jh = 0; jh < 2; jh++) {
                int c = bn + tx * 4 + jh * 64;
                u64 v0 = acc[ih * 4 + i][jh * 2 + 0];
                u64 v1 = acc[ih * 4 + i][jh * 2 + 1];
                mul2(v0, v0, alpha2);
                mul2(v1, v1, alpha2);
                if (bias) {
                    ulonglong2 bb = *(const ulonglong2*)(&bias[c]);
                    add2(v0, v0, bb.x);
                    add2(v1, v1, bb.y);
                }
                ulonglong2 ov; ov.x = v0; ov.y = v1;
                *(ulonglong2*)(C + (long long)r * ldc + c) = ov;
            }
        }
    }
}

// ---------------------------------------------------------------------------
// AV GEMM (NN): C[m,n] = sum_k P[m,k] * V[k,n] per (b,h) batch.
// M=2048, N=64, K=2048. 128x64 tile, BK=8, 128 threads, 8x8 outputs as
// 8x4 packed f32x2 accumulators. Double-buffered + prefetch.
// ---------------------------------------------------------------------------
__global__ __launch_bounds__(128)
void gemm_av(const float* __restrict__ P, const float* __restrict__ V,
             float* __restrict__ C)
{
    int z  = blockIdx.z;
    int bq = z / Hq, hq = z % Hq;
    const float* Ab = P + (long long)z * Lq * Lq;
    const float* Bb = V + (long long)bq * Lq * Dq + hq * HDq;
    float*       Cb = C + (long long)bq * Lq * Dq + hq * HDq;

    const int bm = blockIdx.x * 128;

    __shared__ float As[2][8][128];
    __shared__ float Bs[2][8][64];

    const int tid = threadIdx.x;
    const int tx  = tid & 7;    // N: cols tx*4 and 32+tx*4
    const int ty  = tid >> 3;   // M: rows ty*4.. and 64+ty*4..

    const float* Ap = Ab + (long long)(bm + tid) * Lq;
    const int bvr = tid >> 4;
    const int bvc = (tid & 15) * 4;
    const float* Bp = Bb + (long long)bvr * Dq + bvc;

    u64 acc[8][4];
#pragma unroll
    for (int i = 0; i < 8; i++)
#pragma unroll
        for (int j = 0; j < 4; j++) acc[i][j] = 0ull;

    // Prologue: fill buffer 0
    float4 a0 = *(const float4*)(Ap);
    float4 a1 = *(const float4*)(Ap + 4);
    float4 b0 = *(const float4*)(Bp);
    As[0][0][tid] = a0.x; As[0][1][tid] = a0.y;
    As[0][2][tid] = a0.z; As[0][3][tid] = a0.w;
    As[0][4][tid] = a1.x; As[0][5][tid] = a1.y;
    As[0][6][tid] = a1.z; As[0][7][tid] = a1.w;
    *(float4*)(&Bs[0][bvr][bvc]) = b0;
    __syncthreads();

    int p = 0;
    for (int k0 = 0; k0 < Lq; k0 += 8) {
        const bool nxt = (k0 + 8) < Lq;
        if (nxt) {
            a0 = *(const float4*)(Ap + k0 + 8);
            a1 = *(const float4*)(Ap + k0 + 12);
            b0 = *(const float4*)(Bp + (long long)(k0 + 8) * Dq);
        }
#pragma unroll
        for (int kk = 0; kk < 8; kk++) {
            float ar[8];
            *(float4*)(ar)     = *(const float4*)(&As[p][kk][ty * 4]);
            *(float4*)(ar + 4) = *(const float4*)(&As[p][kk][ty * 4 + 64]);
            ulonglong2 bl0 = *(const ulonglong2*)(&Bs[p][kk][tx * 4]);
            ulonglong2 bl1 = *(const ulonglong2*)(&Bs[p][kk][tx * 4 + 32]);
            u64 bb[4] = { bl0.x, bl0.y, bl1.x, bl1.y };
#pragma unroll
            for (int i = 0; i < 8; i++) {
                u64 ad = dup2(ar[i]);
#pragma unroll
                for (int j = 0; j < 4; j++) fma2(acc[i][j], ad, bb[j]);
            }
        }
        if (nxt) {
            p ^= 1;
            As[p][0][tid] = a0.x; As[p][1][tid] = a0.y;
            As[p][2][tid] = a0.z; As[p][3][tid] = a0.w;
            As[p][4][tid] = a1.x; As[p][5][tid] = a1.y;
            As[p][6][tid] = a1.z; As[p][7][tid] = a1.w;
            *(float4*)(&Bs[p][bvr][bvc]) = b0;
            __syncthreads();
        }
    }

#pragma unroll
    for (int ih = 0; ih < 2; ih++) {
#pragma unroll
        for (int i = 0; i < 4; i++) {
            int r = bm + ih * 64 + ty * 4 + i;
            ulonglong2 ov0, ov1;
            ov0.x = acc[ih * 4 + i][0]; ov0.y = acc[ih * 4 + i][1];
            ov1.x = acc[ih * 4 + i][2]; ov1.y = acc[ih * 4 + i][3];
            *(ulonglong2*)(&Cb[(long long)r * Dq + tx * 4])      = ov0;
            *(ulonglong2*)(&Cb[(long long)r * Dq + 32 + tx * 4]) = ov1;
        }
    }
}

// ---------------------------------------------------------------------------
// Row softmax in place: one block (256 threads) per row of length 2048.
// ---------------------------------------------------------------------------
__global__ __launch_bounds__(256)
void softmax_rows(float* __restrict__ P)
{
    float* p = P + (long long)blockIdx.x * Lq;
    const int tid = threadIdx.x;

    float4 v0 = *(const float4*)(p + tid * 8);
    float4 v1 = *(const float4*)(p + tid * 8 + 4);
    float x[8] = { v0.x, v0.y, v0.z, v0.w, v1.x, v1.y, v1.z, v1.w };

    float m = x[0];
#pragma unroll
    for (int i = 1; i < 8; i++) m = fmaxf(m, x[i]);
#pragma unroll
    for (int o = 16; o; o >>= 1) m = fmaxf(m, __shfl_xor_sync(0xffffffffu, m, o));

    __shared__ float rmax[8];
    __shared__ float rsum[8];
    if ((tid & 31) == 0) rmax[tid >> 5] = m;
    __syncthreads();
    float bmax = rmax[0];
#pragma unroll
    for (int i = 1; i < 8; i++) bmax = fmaxf(bmax, rmax[i]);

    float s = 0.f;
#pragma unroll
    for (int i = 0; i < 8; i++) { x[i] = expf(x[i] - bmax); s += x[i]; }
#pragma unroll
    for (int o = 16; o; o >>= 1) s += __shfl_xor_sync(0xffffffffu, s, o);
    if ((tid & 31) == 0) rsum[tid >> 5] = s;
    __syncthreads();
    float tot = 0.f;
#pragma unroll
    for (int i = 0; i < 8; i++) tot += rsum[i];

    float inv = 1.0f / tot;
#pragma unroll
    for (int i = 0; i < 8; i++) x[i] *= inv;

    *(float4*)(p + tid * 8)     = make_float4(x[0], x[1], x[2], x[3]);
    *(float4*)(p + tid * 8 + 4) = make_float4(x[4], x[5], x[6], x[7]);
}

// ---------------------------------------------------------------------------
// Launch
// ---------------------------------------------------------------------------
extern "C" void kernel_launch(void* const* d_in, const int* in_sizes, int n_in,
                              void* d_out, int out_size)
{
    const float* query = (const float*)d_in[0];
    const float* key   = (const float*)d_in[1];
    const float* value = (const float*)d_in[2];
    const float* Wq    = (const float*)d_in[3];
    const float* Wk    = (const float*)d_in[4];
    const float* Wv    = (const float*)d_in[5];
    const float* Wo    = (const float*)d_in[6];
    const float* bo    = (const float*)d_in[7];

    float* out = (float*)d_out;

    const long long BLD  = (long long)Bq * Lq * Dq;              // 8,388,608
    const long long BHLL = (long long)Bq * Hq * Lq * Lq;         // 268,435,456

    float *pq, *pk, *pv, *poh, *pattn_scratch;
    cudaGetSymbolAddress((void**)&pq,  g_q);
    cudaGetSymbolAddress((void**)&pk,  g_k);
    cudaGetSymbolAddress((void**)&pv,  g_v);
    cudaGetSymbolAddress((void**)&poh, g_oh);
    cudaGetSymbolAddress((void**)&pattn_scratch, g_attn);

    float* attn = ((long long)out_size >= BLD + BHLL) ? (out + BLD)
                                                      : pattn_scratch;

    dim3 blk(256);

    // 1) QKV projections: X[8192,1024] @ W^T[1024,1024]
    {
        dim3 grd(Dq / 128, (Bq * Lq) / 128, 1);
        gemm_nt<<<grd, blk>>>(query, Wq, pq, Dq, Dq, Dq, Dq,
                              0, 0, 0, 0, 0, 0, 1, 1.0f, (const float*)0);
        gemm_nt<<<grd, blk>>>(key,   Wk, pk, Dq, Dq, Dq, Dq,
                              0, 0, 0, 0, 0, 0, 1, 1.0f, (const float*)0);
        gemm_nt<<<grd, blk>>>(value, Wv, pv, Dq, Dq, Dq, Dq,
                              0, 0, 0, 0, 0, 0, 1, 1.0f, (const float*)0);
    }

    // 2) Scores: per (b,h): S = (1/8) * Q_bh @ K_bh^T
    {
        dim3 grd(Lq / 128, Lq / 128, Bq * Hq);
        gemm_nt<<<grd, blk>>>(pq, pk, attn, HDq, Dq, Dq, Lq,
                              (long long)Lq * Dq, (long long)HDq,
                              (long long)Lq * Dq, (long long)HDq,
                              (long long)Hq * Lq * Lq, (long long)Lq * Lq,
                              Hq, 0.125f, (const float*)0);
    }

    // 3) Softmax in place over each length-2048 row
    softmax_rows<<<Bq * Hq * Lq, blk>>>(attn);

    // 4) out_head = attention @ V, written into [B,L,D] layout
    {
        dim3 grd(Lq / 128, 1, Bq * Hq);
        gemm_av<<<grd, dim3(128)>>>(attn, pv, poh);
    }

    // 5) Output projection: out = out_head @ Wo^T + bo
    {
        dim3 grd(Dq / 128, (Bq * Lq) / 128, 1);
        gemm_nt<<<grd, blk>>>(poh, Wo, out, Dq, Dq, Dq, Dq,
                              0, 0, 0, 0, 0, 0, 1, 1.0f, bo);
    }
}